// round 3
// baseline (speedup 1.0000x reference)
#include <cuda_runtime.h>
#include <math.h>

#define NB 64
#define HH 224
#define WW 224
#define C1 24
#define C2 48
#define H2 112
#define H4 56
#define EPSV 1e-5f
#define K2LEN 150528   /* C2*H4*H4 */
#define KCH 512
#define NCHUNK 294     /* 294*512 = 150528 */

// ---------------- scratch (static __device__, no allocation) ----------------
__device__ float g_x1[NB*C1*H2*H2];          // 77 MB  pooled conv1 output
__device__ float g_y2[NB*C2*H2*H2];          // 154 MB pre-BN conv2 output
__device__ float g_x2[NB*C2*H4*H4];          // 38.5 MB pooled conv2 output
__device__ double g_s1[C1*64];               // stride 64 doubles = 512B -> distinct LTS slices
__device__ double g_q1[C1*64];
__device__ double g_s2[C2*64];
__device__ double g_q2[C2*64];
__device__ float g_bn1s[C1], g_bn1b[C1];
__device__ float g_bn2s[C2], g_bn2b[C2];
__device__ float g_part[NCHUNK*NB*C2];
__device__ float g_feat[NB*C2];
__device__ float g_theta[NB*6];

// ---------------- zero accumulators (graph replays need clean state) --------
__global__ void k_zero() {
    int i = blockIdx.x*256 + threadIdx.x;
    if (i < C1*64) { g_s1[i] = 0.0; g_q1[i] = 0.0; }
    if (i < C2*64) { g_s2[i] = 0.0; g_q2[i] = 0.0; }
}

// ---------------- conv1 statistics pass (no store of 308MB tensor) ----------
// quad = 4 horizontally-adjacent output pixels; 4 quads per thread.
__global__ void __launch_bounds__(256) k_conv1_stats(const float* __restrict__ x,
        const float* __restrict__ w, const float* __restrict__ bias) {
    __shared__ float ws[C1*9];
    __shared__ float wb[C1];
    for (int i = threadIdx.x; i < C1*9; i += 256) ws[i] = w[i];
    if (threadIdx.x < C1) wb[threadIdx.x] = bias[threadIdx.x];
    __syncthreads();

    float sum[C1], sq[C1];
#pragma unroll
    for (int c = 0; c < C1; c++) { sum[c] = 0.f; sq[c] = 0.f; }

    const int nthreads = 784*256;           // * 4 iters = 802816 quads exactly
    int t0 = blockIdx.x*256 + threadIdx.x;
#pragma unroll 1
    for (int it = 0; it < 4; it++) {
        int q = t0 + it*nthreads;
        int b   = q / (HH*56);
        int rem = q - b*(HH*56);
        int row = rem / 56;
        int qc  = rem - row*56;
        const float* xb = x + b*HH*WW;
        float tap[3][6];
#pragma unroll
        for (int r = 0; r < 3; r++) {
            int gy = row - 1 + r;
            bool vy = (unsigned)gy < HH;
#pragma unroll
            for (int cc = 0; cc < 6; cc++) {
                int gx = qc*4 - 1 + cc;
                tap[r][cc] = (vy && (unsigned)gx < WW) ? xb[gy*WW + gx] : 0.f;
            }
        }
#pragma unroll
        for (int c = 0; c < C1; c++) {
            float v0 = wb[c], v1 = wb[c], v2 = wb[c], v3 = wb[c];
#pragma unroll
            for (int r = 0; r < 3; r++)
#pragma unroll
            for (int k = 0; k < 3; k++) {
                float wv = ws[c*9 + r*3 + k];
                v0 = fmaf(wv, tap[r][k+0], v0);
                v1 = fmaf(wv, tap[r][k+1], v1);
                v2 = fmaf(wv, tap[r][k+2], v2);
                v3 = fmaf(wv, tap[r][k+3], v3);
            }
            sum[c] += (v0+v1) + (v2+v3);
            sq[c]   = fmaf(v0,v0, fmaf(v1,v1, fmaf(v2,v2, fmaf(v3,v3, sq[c]))));
        }
    }
#pragma unroll
    for (int c = 0; c < C1; c++) {
        float s = sum[c], t = sq[c];
        for (int o = 16; o > 0; o >>= 1) {
            s += __shfl_down_sync(0xffffffffu, s, o);
            t += __shfl_down_sync(0xffffffffu, t, o);
        }
        if ((threadIdx.x & 31) == 0) {
            atomicAdd(&g_s1[c*64], (double)s);
            atomicAdd(&g_q1[c*64], (double)t);
        }
    }
}

__global__ void k_fin1(const float* __restrict__ g, const float* __restrict__ b) {
    int c = threadIdx.x;
    if (c >= C1) return;
    double N = (double)NB*HH*WW;
    double m = g_s1[c*64] / N;
    double v = g_q1[c*64] / N - m*m;
    float sc = g[c] * rsqrtf((float)v + EPSV);
    g_bn1s[c] = sc;
    g_bn1b[c] = b[c] - (float)m * sc;
}

// ---------------- conv1 apply + BN + ReLU + maxpool2 ------------------------
// one thread per pooled pixel, all 24 channels.
__global__ void __launch_bounds__(256) k_conv1_apply(const float* __restrict__ x,
        const float* __restrict__ w, const float* __restrict__ bias) {
    __shared__ float ws[C1*9];
    __shared__ float wb[C1], bs[C1], bb[C1];
    for (int i = threadIdx.x; i < C1*9; i += 256) ws[i] = w[i];
    if (threadIdx.x < C1) {
        wb[threadIdx.x] = bias[threadIdx.x];
        bs[threadIdx.x] = g_bn1s[threadIdx.x];
        bb[threadIdx.x] = g_bn1b[threadIdx.x];
    }
    __syncthreads();

    int idx = blockIdx.x*256 + threadIdx.x;   // 64*112*112 exact
    int b   = idx / (H2*H2);
    int rem = idx - b*(H2*H2);
    int py  = rem / H2;
    int px  = rem - py*H2;
    const float* xb = x + b*HH*WW;

    float tap[4][4];
#pragma unroll
    for (int r = 0; r < 4; r++) {
        int gy = 2*py - 1 + r;
        bool vy = (unsigned)gy < HH;
#pragma unroll
        for (int cc = 0; cc < 4; cc++) {
            int gx = 2*px - 1 + cc;
            tap[r][cc] = (vy && (unsigned)gx < WW) ? xb[gy*WW + gx] : 0.f;
        }
    }
    float* o1 = g_x1 + b*C1*H2*H2 + py*H2 + px;
#pragma unroll
    for (int c = 0; c < C1; c++) {
        float v00 = wb[c], v01 = wb[c], v10 = wb[c], v11 = wb[c];
#pragma unroll
        for (int r = 0; r < 3; r++)
#pragma unroll
        for (int k = 0; k < 3; k++) {
            float wv = ws[c*9 + r*3 + k];
            v00 = fmaf(wv, tap[r  ][k  ], v00);
            v01 = fmaf(wv, tap[r  ][k+1], v01);
            v10 = fmaf(wv, tap[r+1][k  ], v10);
            v11 = fmaf(wv, tap[r+1][k+1], v11);
        }
        float sc = bs[c], sh = bb[c];
        float m = fmaxf(fmaxf(fmaf(v00,sc,sh), fmaf(v01,sc,sh)),
                        fmaxf(fmaf(v10,sc,sh), fmaf(v11,sc,sh)));
        o1[c*H2*H2] = fmaxf(m, 0.f);
    }
}

// ---------------- conv2 (24->48, 3x3) + fused BN stats ----------------------
// block: 16x8 pixel tile of one image, all 48 co. thread: 6 co x 4 px.
__global__ void __launch_bounds__(256) k_conv2(const float* __restrict__ wt,
                                               const float* __restrict__ bias) {
    __shared__ float Is[C1*200];   // 24 ci x 10 rows x (18 used, stride 20) = 19.2 KB
    __shared__ float Ws[108*C2];   // 12 ci x 9 taps x 48 co = 20.7 KB

    int blk = blockIdx.x;                // 64 * 98
    int b   = blk / 98;
    int rem = blk - b*98;
    int tqy = rem / 7;
    int ty  = tqy * 8;
    int tx  = (rem - tqy*7) * 16;

    const float* x1b = g_x1 + b*C1*H2*H2;
    for (int i = threadIdx.x; i < C1*180; i += 256) {
        int ci = i / 180;
        int r2 = i - ci*180;
        int r  = r2 / 18;
        int c  = r2 - r*18;
        int gy = ty - 1 + r;
        int gx = tx - 1 + c;
        float v = ((unsigned)gy < H2 && (unsigned)gx < H2) ? x1b[(ci*H2 + gy)*H2 + gx] : 0.f;
        Is[ci*200 + r*20 + c] = v;
    }

    int lane  = threadIdx.x & 31;
    int warp  = threadIdx.x >> 5;        // warp == co-group
    int colx  = lane & 15;
    int rbase = (lane >> 4) << 2;        // 0 or 4 -> +80 floats = disjoint bank halves

    float acc[6][4];
#pragma unroll
    for (int j = 0; j < 6; j++)
#pragma unroll
    for (int i = 0; i < 4; i++) acc[j][i] = 0.f;

#pragma unroll 1
    for (int g = 0; g < 2; g++) {
        __syncthreads();
        for (int i = threadIdx.x; i < 108*C2; i += 256) {
            int co = i / 108;
            int kk = i - co*108;
            Ws[kk*C2 + co] = wt[co*216 + g*108 + kk];   // coalesced read
        }
        __syncthreads();
#pragma unroll 1
        for (int cl = 0; cl < 12; cl++) {
            const float* Ip = Is + (g*12 + cl)*200;
#pragma unroll
            for (int ky = 0; ky < 3; ky++) {
#pragma unroll
                for (int kx = 0; kx < 3; kx++) {
                    const float* Wp = Ws + (cl*9 + ky*3 + kx)*C2 + warp*6;
                    float wv[6], iv[4];
#pragma unroll
                    for (int j = 0; j < 6; j++) wv[j] = Wp[j];       // broadcast LDS
#pragma unroll
                    for (int i = 0; i < 4; i++)
                        iv[i] = Ip[(rbase + ky + i)*20 + colx + kx]; // conflict-free
#pragma unroll
                    for (int j = 0; j < 6; j++)
#pragma unroll
                    for (int i = 0; i < 4; i++)
                        acc[j][i] = fmaf(wv[j], iv[i], acc[j][i]);
                }
            }
        }
    }

    float* y2b = g_y2 + b*C2*H2*H2;
#pragma unroll
    for (int j = 0; j < 6; j++) {
        int co = warp*6 + j;
        float bco = __ldg(&bias[co]);
        float s = 0.f, qq = 0.f;
#pragma unroll
        for (int i = 0; i < 4; i++) {
            float v = acc[j][i] + bco;
            y2b[(co*H2 + ty + rbase + i)*H2 + tx + colx] = v;
            s += v;
            qq = fmaf(v, v, qq);
        }
        for (int o = 16; o > 0; o >>= 1) {
            s  += __shfl_down_sync(0xffffffffu, s,  o);
            qq += __shfl_down_sync(0xffffffffu, qq, o);
        }
        if (lane == 0) {
            atomicAdd(&g_s2[co*64], (double)s);
            atomicAdd(&g_q2[co*64], (double)qq);
        }
    }
}

__global__ void k_fin2(const float* __restrict__ g, const float* __restrict__ b) {
    int c = threadIdx.x;
    if (c >= C2) return;
    double N = (double)NB*H2*H2;
    double m = g_s2[c*64] / N;
    double v = g_q2[c*64] / N - m*m;
    float sc = g[c] * rsqrtf((float)v + EPSV);
    g_bn2s[c] = sc;
    g_bn2b[c] = b[c] - (float)m * sc;
}

// ---------------- BN2 + ReLU + maxpool2 -------------------------------------
__global__ void k_pool2() {
    int idx = blockIdx.x*256 + threadIdx.x;      // 64*48*56*56 exact
    int b   = idx / (C2*H4*H4);
    int rem = idx - b*(C2*H4*H4);
    int c   = rem / (H4*H4);
    int r2  = rem - c*(H4*H4);
    int py  = r2 / H4;
    int px  = r2 - py*H4;
    const float* y = g_y2 + ((b*C2 + c)*H2 + 2*py)*H2 + 2*px;
    float sc = g_bn2s[c], sh = g_bn2b[c];
    float m = fmaxf(fmaxf(fmaf(y[0],   sc, sh), fmaf(y[1],    sc, sh)),
                    fmaxf(fmaf(y[H2],  sc, sh), fmaf(y[H2+1], sc, sh)));
    g_x2[idx] = fmaxf(m, 0.f);
}

// ---------------- feat GEMM (64x48, K=150528) split-K, deterministic --------
__global__ void __launch_bounds__(256) k_feat_part(const float* __restrict__ fw) {
    __shared__ float xs[NB*33];
    __shared__ float wsm[C2*33];
    int k0  = blockIdx.x * KCH;
    int tid = threadIdx.x;
    int bi  = tid & 15;     // b-group (4 b each)
    int oi  = tid >> 4;     // o-group (3 o each)
    int kl  = tid & 31;
    int rr  = tid >> 5;
    float acc[4][3];
#pragma unroll
    for (int i = 0; i < 4; i++)
#pragma unroll
    for (int j = 0; j < 3; j++) acc[i][j] = 0.f;

#pragma unroll 1
    for (int kk = 0; kk < KCH; kk += 32) {
        __syncthreads();
#pragma unroll
        for (int r = 0; r < 8; r++) {
            int bb = r*8 + rr;
            xs[bb*33 + kl] = g_x2[bb*K2LEN + k0 + kk + kl];
        }
#pragma unroll
        for (int r = 0; r < 6; r++) {
            int oo = r*8 + rr;
            wsm[oo*33 + kl] = fw[(size_t)oo*K2LEN + k0 + kk + kl];
        }
        __syncthreads();
#pragma unroll
        for (int k = 0; k < 32; k++) {
            float xv[4], wv[3];
#pragma unroll
            for (int i = 0; i < 4; i++) xv[i] = xs[(bi*4 + i)*33 + k];
#pragma unroll
            for (int j = 0; j < 3; j++) wv[j] = wsm[(oi*3 + j)*33 + k];
#pragma unroll
            for (int i = 0; i < 4; i++)
#pragma unroll
            for (int j = 0; j < 3; j++)
                acc[i][j] = fmaf(xv[i], wv[j], acc[i][j]);
        }
    }
#pragma unroll
    for (int i = 0; i < 4; i++)
#pragma unroll
    for (int j = 0; j < 3; j++)
        g_part[(size_t)blockIdx.x*NB*C2 + (bi*4 + i)*C2 + (oi*3 + j)] = acc[i][j];
}

__global__ void k_feat_reduce(const float* __restrict__ fb) {
    int i = blockIdx.x*256 + threadIdx.x;
    if (i >= NB*C2) return;
    float s = 0.f;
    for (int n = 0; n < NCHUNK; n++) s += g_part[n*NB*C2 + i];
    g_feat[i] = s + fb[i % C2];
}

// ---------------- MLP head + theta build + tail outputs ---------------------
__global__ void k_head(const float* __restrict__ l1w, const float* __restrict__ l1b,
                       const float* __restrict__ l2w, const float* __restrict__ l2b,
                       float* __restrict__ out) {
    int b = threadIdx.x;
    if (b >= NB) return;
    float h[24];
#pragma unroll 1
    for (int j = 0; j < 24; j++) {
        float s = l1b[j];
        for (int k = 0; k < 48; k++)
            s = fmaf(l1w[j*48 + k], g_feat[b*48 + k], s);
        h[j] = fmaxf(s, 0.f);
    }
    float t[4];
#pragma unroll
    for (int i = 0; i < 4; i++) {
        float s = l2b[i];
#pragma unroll
        for (int j = 0; j < 24; j++)
            s = fmaf(l2w[i*24 + j], h[j], s);
        t[i] = s;
    }
    float tx = t[0], tyv = t[1], sc = t[2], an = t[3];
    float cs = cosf(an), sn = sinf(an);
    g_theta[b*6 + 0] =  sc*cs;
    g_theta[b*6 + 1] = -sc*sn;
    g_theta[b*6 + 2] =  tx;
    g_theta[b*6 + 3] =  sc*sn;
    g_theta[b*6 + 4] =  sc*cs;
    g_theta[b*6 + 5] =  tyv;
    out[NB*HH*WW +         b] = tx;
    out[NB*HH*WW +  64 +   b] = tyv;
    out[NB*HH*WW + 128 +   b] = sc;
    out[NB*HH*WW + 192 +   b] = an;
}

// ---------------- affine grid + bilinear sample -----------------------------
__device__ __forceinline__ float tapf(const float* __restrict__ xb,
                                      float xf, float yf, float wgt) {
    bool valid = (xf >= 0.f) & (xf < (float)WW) & (yf >= 0.f) & (yf < (float)HH);
    int xi = (int)fminf(fmaxf(xf, 0.f), (float)(WW-1));
    int yi = (int)fminf(fmaxf(yf, 0.f), (float)(HH-1));
    float v = __ldg(&xb[yi*WW + xi]);
    return valid ? v*wgt : 0.f;
}

__global__ void k_sample(const float* __restrict__ x, float* __restrict__ out) {
    int idx = blockIdx.x*256 + threadIdx.x;      // 64*224*224 exact
    int b   = idx / (HH*WW);
    int rem = idx - b*(HH*WW);
    int r   = rem / WW;
    int c   = rem - r*WW;
    float xsn = (2.f*c + 1.f)/(float)WW - 1.f;
    float ysn = (2.f*r + 1.f)/(float)HH - 1.f;
    const float* th = g_theta + b*6;
    float gx = th[0]*xsn + th[1]*ysn + th[2];
    float gy = th[3]*xsn + th[4]*ysn + th[5];
    float ix = ((gx + 1.f)*(float)WW - 1.f)*0.5f;
    float iy = ((gy + 1.f)*(float)HH - 1.f)*0.5f;
    float x0 = floorf(ix), y0 = floorf(iy);
    float x1 = x0 + 1.f,   y1 = y0 + 1.f;
    float wx1 = ix - x0, wx0 = 1.f - wx1;
    float wy1 = iy - y0, wy0 = 1.f - wy1;
    const float* xb = x + b*HH*WW;
    float o = tapf(xb, x0, y0, wx0*wy0)
            + tapf(xb, x1, y0, wx1*wy0)
            + tapf(xb, x0, y1, wx0*wy1)
            + tapf(xb, x1, y1, wx1*wy1);
    out[idx] = o;
}

// ---------------- launch ----------------------------------------------------
extern "C" void kernel_launch(void* const* d_in, const int* in_sizes, int n_in,
                              void* d_out, int out_size) {
    (void)in_sizes; (void)n_in; (void)out_size;
    const float* x    = (const float*)d_in[0];
    const float* c1w  = (const float*)d_in[1];
    const float* c1b  = (const float*)d_in[2];
    const float* bn1g = (const float*)d_in[3];
    const float* bn1b = (const float*)d_in[4];
    const float* c2w  = (const float*)d_in[5];
    const float* c2b  = (const float*)d_in[6];
    const float* bn2g = (const float*)d_in[7];
    const float* bn2b = (const float*)d_in[8];
    const float* fw   = (const float*)d_in[9];
    const float* fb   = (const float*)d_in[10];
    const float* l1w  = (const float*)d_in[11];
    const float* l1b  = (const float*)d_in[12];
    const float* l2w  = (const float*)d_in[13];
    const float* l2b  = (const float*)d_in[14];
    float* out = (float*)d_out;

    k_zero<<<12, 256>>>();
    k_conv1_stats<<<784, 256>>>(x, c1w, c1b);
    k_fin1<<<1, 32>>>(bn1g, bn1b);
    k_conv1_apply<<<3136, 256>>>(x, c1w, c1b);
    k_conv2<<<NB*98, 256>>>(c2w, c2b);
    k_fin2<<<1, 64>>>(bn2g, bn2b);
    k_pool2<<<(NB*C2*H4*H4)/256, 256>>>();
    k_feat_part<<<NCHUNK, 256>>>(fw);
    k_feat_reduce<<<12, 256>>>(fb);
    k_head<<<1, 64>>>(l1w, l1b, l2w, l2b, out);
    k_sample<<<(NB*HH*WW)/256, 256>>>(x, out);
}